// round 8
// baseline (speedup 1.0000x reference)
#include <cuda_runtime.h>
#include <cstdint>

// Problem constants (fixed-shape problem)
#define B_SZ   4
#define T_SEQ  2048
#define E_DIM  1024
#define NH     16
#define HD     64
#define M_TOT  (B_SZ * T_SEQ)   // 8192

// ---------------------------------------------------------------------------
// Scratch (allocation-free rule: __device__ globals)
// ---------------------------------------------------------------------------
__device__ float g_q[(size_t)M_TOT * E_DIM];    // [B,H,T,D]
__device__ float g_k[(size_t)M_TOT * E_DIM];    // [B,H,T,D]
__device__ float g_v[(size_t)M_TOT * E_DIM];    // [B,H,T,D]
__device__ float g_ctx[(size_t)M_TOT * E_DIM];  // [B,T,E]

// ---------------------------------------------------------------------------
// helpers
// ---------------------------------------------------------------------------
__device__ __forceinline__ uint32_t f2tf(float x) {
    uint32_t r;
    asm("cvt.rna.tf32.f32 %0, %1;" : "=r"(r) : "f"(x));
    return r;
}
__device__ __forceinline__ float ex2(float x) {
    float r;
    asm("ex2.approx.f32 %0, %1;" : "=f"(r) : "f"(x));
    return r;
}
__device__ __forceinline__ void mma8(float* c, const uint32_t* a, const uint32_t* b) {
    asm volatile(
        "mma.sync.aligned.m16n8k8.row.col.f32.tf32.tf32.f32 "
        "{%0,%1,%2,%3}, {%4,%5,%6,%7}, {%8,%9}, {%0,%1,%2,%3};\n"
        : "+f"(c[0]), "+f"(c[1]), "+f"(c[2]), "+f"(c[3])
        : "r"(a[0]), "r"(a[1]), "r"(a[2]), "r"(a[3]), "r"(b[0]), "r"(b[1]));
}
__device__ __forceinline__ uint32_t smaddr(const void* p) {
    return (uint32_t)__cvta_generic_to_shared(p);
}
__device__ __forceinline__ void cp16(uint32_t dst, const void* src) {
    asm volatile("cp.async.ca.shared.global [%0], [%1], 16;\n" :: "r"(dst), "l"(src));
}
__device__ __forceinline__ void cpcommit() {
    asm volatile("cp.async.commit_group;\n");
}
template<int N>
__device__ __forceinline__ void cpwait() {
    asm volatile("cp.async.wait_group %0;\n" :: "n"(N));
}

// ---------------------------------------------------------------------------
// GEMM: Y = X @ W^T + bias. Block tile 128x128, BK=32, double-buffered
// cp.async, 256 threads = 8 warps (4 M x 2 N), warp tile 32x64.
// fp32 in smem; cvt to tf32 at fragment-load time.
// split=1: write Y in [B,H,T,D]; split=0: plain [M,E].
// smem: As[2][128][36] + Bs[2][128][36] = 73728 B (dynamic).
// ---------------------------------------------------------------------------
#define G_AS (128 * 36)
__global__ __launch_bounds__(256) void gemm_bias(
    const float* __restrict__ X, const float* __restrict__ W,
    const float* __restrict__ bias, float* __restrict__ Y, int split)
{
    extern __shared__ float sm[];
    float* As = sm;              // [2][128][36]
    float* Bs = sm + 2 * G_AS;   // [2][128][36]

    const int tid  = threadIdx.x;
    const int warp = tid >> 5, lane = tid & 31;
    const int wm   = warp >> 1, wn = warp & 1;
    const int g    = lane >> 2, t = lane & 3;
    const int m0   = blockIdx.x * 128;
    const int n0   = blockIdx.y * 128;

    auto issue = [&](int k0, int buf) {
        const float* Ag = X + (size_t)m0 * E_DIM + k0;
        const float* Bg = W + (size_t)n0 * E_DIM + k0;
        float* dA = As + buf * G_AS;
        float* dB = Bs + buf * G_AS;
#pragma unroll
        for (int i = 0; i < 4; i++) {
            int idx = tid + i * 256;          // 0..1023
            int r = idx >> 3, c4 = idx & 7;
            cp16(smaddr(dA + r * 36 + c4 * 4), Ag + (size_t)r * E_DIM + c4 * 4);
        }
#pragma unroll
        for (int i = 0; i < 4; i++) {
            int idx = tid + i * 256;
            int r = idx >> 3, c4 = idx & 7;
            cp16(smaddr(dB + r * 36 + c4 * 4), Bg + (size_t)r * E_DIM + c4 * 4);
        }
        cpcommit();
    };

    float acc[2][8][4];
#pragma unroll
    for (int i = 0; i < 2; i++)
#pragma unroll
        for (int j = 0; j < 8; j++)
#pragma unroll
            for (int r = 0; r < 4; r++) acc[i][j][r] = 0.f;

    issue(0, 0);

    for (int ks = 0; ks < 32; ks++) {
        if (ks + 1 < 32) { issue((ks + 1) * 32, (ks + 1) & 1); cpwait<1>(); }
        else             { cpwait<0>(); }
        __syncthreads();

        const float* A = As + (ks & 1) * G_AS;
        const float* Bt = Bs + (ks & 1) * G_AS;

#pragma unroll
        for (int kk = 0; kk < 32; kk += 8) {
            uint32_t a[2][4];
#pragma unroll
            for (int mt = 0; mt < 2; mt++) {
                int row = wm * 32 + mt * 16;
                a[mt][0] = f2tf(A[(row + g)     * 36 + kk + t]);
                a[mt][1] = f2tf(A[(row + 8 + g) * 36 + kk + t]);
                a[mt][2] = f2tf(A[(row + g)     * 36 + kk + t + 4]);
                a[mt][3] = f2tf(A[(row + 8 + g) * 36 + kk + t + 4]);
            }
#pragma unroll
            for (int nt = 0; nt < 8; nt++) {
                int col = wn * 64 + nt * 8 + g;
                uint32_t b[2];
                b[0] = f2tf(Bt[col * 36 + kk + t]);
                b[1] = f2tf(Bt[col * 36 + kk + t + 4]);
                mma8(acc[0][nt], a[0], b);
                mma8(acc[1][nt], a[1], b);
            }
        }
        __syncthreads();
    }

    // Epilogue: bias + writeout
#pragma unroll
    for (int mt = 0; mt < 2; mt++) {
#pragma unroll
        for (int nt = 0; nt < 8; nt++) {
            int mrow = m0 + wm * 32 + mt * 16 + g;
            int ncol = n0 + wn * 64 + nt * 8 + 2 * t;
            float b0 = bias[ncol], b1 = bias[ncol + 1];
            float v00 = acc[mt][nt][0] + b0, v01 = acc[mt][nt][1] + b1;
            float v10 = acc[mt][nt][2] + b0, v11 = acc[mt][nt][3] + b1;
            if (!split) {
                float* p0 = Y + (size_t)mrow * E_DIM + ncol;
                float* p1 = Y + (size_t)(mrow + 8) * E_DIM + ncol;
                p0[0] = v00; p0[1] = v01;
                p1[0] = v10; p1[1] = v11;
            } else {
                int h = ncol >> 6, d = ncol & 63;
                int bb = mrow >> 11, tt = mrow & 2047;
                size_t o0 = ((size_t)(bb * NH + h) * T_SEQ + tt) * HD + d;
                size_t o1 = o0 + 8 * HD;
                Y[o0] = v00; Y[o0 + 1] = v01;
                Y[o1] = v10; Y[o1 + 1] = v11;
            }
        }
    }
}

// ---------------------------------------------------------------------------
// Flash attention: grid (T/128, B*H), 128 threads (4 warps).
// Each warp owns 32 query rows (2 m16 tiles); block = 128 queries.
// K/V streamed in 32-key tiles, double-buffered via cp.async (fp32 in smem,
// cvt at fragment load). P C-frag -> A-frag via register shuffles (no smem).
// smem: sQ[128][68] + sK[2][32][68] + sV[2][32][72] = 70656 B (dynamic).
// ---------------------------------------------------------------------------
#define A_SQ  (128 * 68)
#define A_SKB (32 * 68)
#define A_SVB (32 * 72)
__global__ __launch_bounds__(128) void attn_kernel(
    const float* __restrict__ Q, const float* __restrict__ K,
    const float* __restrict__ V, float* __restrict__ O)
{
    extern __shared__ float sm[];
    float* sQ = sm;                     // [128][68]
    float* sK = sm + A_SQ;              // [2][32][68]
    float* sV = sK + 2 * A_SKB;         // [2][32][72]

    const int tid  = threadIdx.x;
    const int warp = tid >> 5, lane = tid & 31;
    const int g    = lane >> 2, t = lane & 3;
    const int q0   = blockIdx.x * 128;
    const int bh   = blockIdx.y;

    const float* Qb = Q + ((size_t)bh * T_SEQ + q0) * HD;
    const float* Kb = K + (size_t)bh * T_SEQ * HD;
    const float* Vb = V + (size_t)bh * T_SEQ * HD;

    auto issueKV = [&](int j, int buf) {
        const float* Kg = Kb + (size_t)j * 32 * HD;
        const float* Vg = Vb + (size_t)j * 32 * HD;
        float* dK = sK + buf * A_SKB;
        float* dV = sV + buf * A_SVB;
#pragma unroll
        for (int i = 0; i < 4; i++) {
            int idx = tid + i * 128;          // 0..511
            int r = idx >> 4, c4 = idx & 15;
            cp16(smaddr(dK + r * 68 + c4 * 4), Kg + r * HD + c4 * 4);
            cp16(smaddr(dV + r * 72 + c4 * 4), Vg + r * HD + c4 * 4);
        }
        cpcommit();
    };

    // Stage Q (group 0), then KV tile 0 (group 1)
#pragma unroll
    for (int i = 0; i < 16; i++) {
        int idx = tid + i * 128;              // 0..2047
        int r = idx >> 4, c4 = idx & 15;
        cp16(smaddr(sQ + r * 68 + c4 * 4), Qb + r * HD + c4 * 4);
    }
    cpcommit();
    issueKV(0, 0);
    cpwait<1>();          // Q complete
    __syncthreads();

    // Cache Q A-frags for m-tile 0 only (m-tile 1 reloaded per tile)
    uint32_t qa[8][4];
    {
        int row = warp * 32;
#pragma unroll
        for (int kd = 0; kd < 8; kd++) {
            qa[kd][0] = f2tf(sQ[(row + g)     * 68 + kd * 8 + t]);
            qa[kd][1] = f2tf(sQ[(row + 8 + g) * 68 + kd * 8 + t]);
            qa[kd][2] = f2tf(sQ[(row + g)     * 68 + kd * 8 + t + 4]);
            qa[kd][3] = f2tf(sQ[(row + 8 + g) * 68 + kd * 8 + t + 4]);
        }
    }

    float mrow[2][2] = {{-1e30f, -1e30f}, {-1e30f, -1e30f}};
    float lrow[2][2] = {{0.f, 0.f}, {0.f, 0.f}};
    float o[2][8][4];
#pragma unroll
    for (int mt = 0; mt < 2; mt++)
#pragma unroll
        for (int df = 0; df < 8; df++)
#pragma unroll
            for (int r = 0; r < 4; r++) o[mt][df][r] = 0.f;

    const float SC = 0.125f * 1.44269504088896f;   // 1/sqrt(64) * log2(e)

    for (int j = 0; j < T_SEQ / 32; j++) {
        if (j + 1 < T_SEQ / 32) { issueKV(j + 1, (j + 1) & 1); cpwait<1>(); }
        else                    { cpwait<0>(); }
        __syncthreads();

        const float* Kt = sK + (j & 1) * A_SKB;
        const float* Vt = sV + (j & 1) * A_SVB;

        // ---- S = Q K^T : 32 q-rows x 32 keys ----
        float s[2][4][4];
#pragma unroll
        for (int mt = 0; mt < 2; mt++)
#pragma unroll
            for (int nt = 0; nt < 4; nt++)
#pragma unroll
                for (int r = 0; r < 4; r++) s[mt][nt][r] = 0.f;

#pragma unroll
        for (int kd = 0; kd < 8; kd++) {
            uint32_t a1[4];
            int row1 = warp * 32 + 16;
            a1[0] = f2tf(sQ[(row1 + g)     * 68 + kd * 8 + t]);
            a1[1] = f2tf(sQ[(row1 + 8 + g) * 68 + kd * 8 + t]);
            a1[2] = f2tf(sQ[(row1 + g)     * 68 + kd * 8 + t + 4]);
            a1[3] = f2tf(sQ[(row1 + 8 + g) * 68 + kd * 8 + t + 4]);
#pragma unroll
            for (int nt = 0; nt < 4; nt++) {
                uint32_t b[2];
                b[0] = f2tf(Kt[(nt * 8 + g) * 68 + kd * 8 + t]);
                b[1] = f2tf(Kt[(nt * 8 + g) * 68 + kd * 8 + t + 4]);
                mma8(s[0][nt], qa[kd], b);
                mma8(s[1][nt], a1, b);
            }
        }

        // ---- online softmax (base-2) ----
#pragma unroll
        for (int mt = 0; mt < 2; mt++) {
            float mx0 = -1e30f, mx1 = -1e30f;
#pragma unroll
            for (int nt = 0; nt < 4; nt++) {
                s[mt][nt][0] *= SC; s[mt][nt][1] *= SC;
                s[mt][nt][2] *= SC; s[mt][nt][3] *= SC;
                mx0 = fmaxf(mx0, fmaxf(s[mt][nt][0], s[mt][nt][1]));
                mx1 = fmaxf(mx1, fmaxf(s[mt][nt][2], s[mt][nt][3]));
            }
            mx0 = fmaxf(mx0, __shfl_xor_sync(0xffffffffu, mx0, 1));
            mx0 = fmaxf(mx0, __shfl_xor_sync(0xffffffffu, mx0, 2));
            mx1 = fmaxf(mx1, __shfl_xor_sync(0xffffffffu, mx1, 1));
            mx1 = fmaxf(mx1, __shfl_xor_sync(0xffffffffu, mx1, 2));

            float mn0 = fmaxf(mrow[mt][0], mx0);
            float mn1 = fmaxf(mrow[mt][1], mx1);
            float al0 = ex2(mrow[mt][0] - mn0);
            float al1 = ex2(mrow[mt][1] - mn1);

            float rs0 = 0.f, rs1 = 0.f;
#pragma unroll
            for (int nt = 0; nt < 4; nt++) {
                s[mt][nt][0] = ex2(s[mt][nt][0] - mn0);
                s[mt][nt][1] = ex2(s[mt][nt][1] - mn0);
                s[mt][nt][2] = ex2(s[mt][nt][2] - mn1);
                s[mt][nt][3] = ex2(s[mt][nt][3] - mn1);
                rs0 += s[mt][nt][0] + s[mt][nt][1];
                rs1 += s[mt][nt][2] + s[mt][nt][3];
            }
            rs0 += __shfl_xor_sync(0xffffffffu, rs0, 1);
            rs0 += __shfl_xor_sync(0xffffffffu, rs0, 2);
            rs1 += __shfl_xor_sync(0xffffffffu, rs1, 1);
            rs1 += __shfl_xor_sync(0xffffffffu, rs1, 2);

            lrow[mt][0] = lrow[mt][0] * al0 + rs0;
            lrow[mt][1] = lrow[mt][1] * al1 + rs1;
            mrow[mt][0] = mn0;
            mrow[mt][1] = mn1;
#pragma unroll
            for (int df = 0; df < 8; df++) {
                o[mt][df][0] *= al0; o[mt][df][1] *= al0;
                o[mt][df][2] *= al1; o[mt][df][3] *= al1;
            }
        }

        // ---- O += P @ V (P C-frag -> A-frag via shuffles) ----
#pragma unroll
        for (int kk = 0; kk < 4; kk++) {
            uint32_t pa[2][4];
            int srcA = (lane & ~3) | (t >> 1);
            int srcB = srcA + 2;
#pragma unroll
            for (int mt = 0; mt < 2; mt++) {
                uint32_t p0 = f2tf(s[mt][kk][0]);
                uint32_t p1 = f2tf(s[mt][kk][1]);
                uint32_t p2 = f2tf(s[mt][kk][2]);
                uint32_t p3 = f2tf(s[mt][kk][3]);
                uint32_t e0, e1;
                e0 = __shfl_sync(0xffffffffu, p0, srcA);
                e1 = __shfl_sync(0xffffffffu, p1, srcA);
                pa[mt][0] = (t & 1) ? e1 : e0;
                e0 = __shfl_sync(0xffffffffu, p2, srcA);
                e1 = __shfl_sync(0xffffffffu, p3, srcA);
                pa[mt][1] = (t & 1) ? e1 : e0;
                e0 = __shfl_sync(0xffffffffu, p0, srcB);
                e1 = __shfl_sync(0xffffffffu, p1, srcB);
                pa[mt][2] = (t & 1) ? e1 : e0;
                e0 = __shfl_sync(0xffffffffu, p2, srcB);
                e1 = __shfl_sync(0xffffffffu, p3, srcB);
                pa[mt][3] = (t & 1) ? e1 : e0;
            }
#pragma unroll
            for (int df = 0; df < 8; df++) {
                uint32_t b[2];
                b[0] = f2tf(Vt[(kk * 8 + t)     * 72 + df * 8 + g]);
                b[1] = f2tf(Vt[(kk * 8 + t + 4) * 72 + df * 8 + g]);
                mma8(o[0][df], pa[0], b);
                mma8(o[1][df], pa[1], b);
            }
        }
        __syncthreads();
    }

    // ---- epilogue: normalize, write [B,T,E] ----
    int bb = bh >> 4, h = bh & 15;
#pragma unroll
    for (int mt = 0; mt < 2; mt++) {
        float inv0 = 1.f / lrow[mt][0];
        float inv1 = 1.f / lrow[mt][1];
        int r0 = q0 + warp * 32 + mt * 16 + g;
#pragma unroll
        for (int df = 0; df < 8; df++) {
            int d = df * 8 + 2 * t;
            size_t base0 = ((size_t)bb * T_SEQ + r0) * E_DIM + h * HD + d;
            size_t base1 = base0 + (size_t)8 * E_DIM;
            O[base0]     = o[mt][df][0] * inv0;
            O[base0 + 1] = o[mt][df][1] * inv0;
            O[base1]     = o[mt][df][2] * inv1;
            O[base1 + 1] = o[mt][df][3] * inv1;
        }
    }
}

// ---------------------------------------------------------------------------
// Launcher
// ---------------------------------------------------------------------------
#define GEMM_SMEM  (4 * G_AS * 4)                        // 73728 B
#define ATTN_SMEM  ((A_SQ + 2 * A_SKB + 2 * A_SVB) * 4)  // 70656 B

extern "C" void kernel_launch(void* const* d_in, const int* in_sizes, int n_in,
                              void* d_out, int out_size)
{
    const float* x  = (const float*)d_in[0];
    const float* Wq = (const float*)d_in[1];
    const float* bq = (const float*)d_in[2];
    const float* Wk = (const float*)d_in[3];
    const float* bk = (const float*)d_in[4];
    const float* Wv = (const float*)d_in[5];
    const float* bv = (const float*)d_in[6];
    const float* Wo = (const float*)d_in[7];
    const float* bo = (const float*)d_in[8];

    float *q, *k, *v, *ctx;
    cudaGetSymbolAddress((void**)&q,   g_q);
    cudaGetSymbolAddress((void**)&k,   g_k);
    cudaGetSymbolAddress((void**)&v,   g_v);
    cudaGetSymbolAddress((void**)&ctx, g_ctx);

    cudaFuncSetAttribute(gemm_bias, cudaFuncAttributeMaxDynamicSharedMemorySize, GEMM_SMEM);
    cudaFuncSetAttribute(attn_kernel, cudaFuncAttributeMaxDynamicSharedMemorySize, ATTN_SMEM);

    dim3 ggrid(M_TOT / 128, E_DIM / 128);   // (64, 8)

    gemm_bias<<<ggrid, 256, GEMM_SMEM>>>(x, Wq, bq, q, 1);
    gemm_bias<<<ggrid, 256, GEMM_SMEM>>>(x, Wk, bk, k, 1);
    gemm_bias<<<ggrid, 256, GEMM_SMEM>>>(x, Wv, bv, v, 1);

    attn_kernel<<<dim3(T_SEQ / 128, B_SZ * NH), 128, ATTN_SMEM>>>(q, k, v, ctx);

    gemm_bias<<<ggrid, 256, GEMM_SMEM>>>(ctx, Wo, bo, (float*)d_out, 0);
}

// round 12
// speedup vs baseline: 1.1117x; 1.1117x over previous
#include <cuda_runtime.h>
#include <cstdint>

// Problem constants (fixed-shape problem)
#define B_SZ   4
#define T_SEQ  2048
#define E_DIM  1024
#define NH     16
#define HD     64
#define M_TOT  (B_SZ * T_SEQ)   // 8192

// ---------------------------------------------------------------------------
// Scratch (allocation-free rule: __device__ globals)
// ---------------------------------------------------------------------------
__device__ float g_q[(size_t)M_TOT * E_DIM];    // [B,H,T,D] (tf32-rounded)
__device__ float g_k[(size_t)M_TOT * E_DIM];    // [B,H,T,D] (tf32-rounded)
__device__ float g_v[(size_t)M_TOT * E_DIM];    // [B,H,T,D] (tf32-rounded)
__device__ float g_ctx[(size_t)M_TOT * E_DIM];  // [B,T,E]   (tf32-rounded)
__device__ float g_x [(size_t)M_TOT * E_DIM];   // tf32-rounded copy of x
__device__ float g_wq[(size_t)E_DIM * E_DIM];   // tf32-rounded weights
__device__ float g_wk[(size_t)E_DIM * E_DIM];
__device__ float g_wv[(size_t)E_DIM * E_DIM];
__device__ float g_wo[(size_t)E_DIM * E_DIM];

// ---------------------------------------------------------------------------
// helpers
// ---------------------------------------------------------------------------
// All MMA operands are RNA-rounded to tf32 BEFORE they reach smem/registers,
// so the inner loops feed raw fp32 bit patterns (hardware truncation of an
// already-rounded value is exact).
__device__ __forceinline__ uint32_t ftu(float x) { return __float_as_uint(x); }

__device__ __forceinline__ float rnd_tf32(float x) {
    uint32_t r;
    asm("cvt.rna.tf32.f32 %0, %1;" : "=r"(r) : "f"(x));
    return __uint_as_float(r);
}
__device__ __forceinline__ float ex2(float x) {
    float r;
    asm("ex2.approx.f32 %0, %1;" : "=f"(r) : "f"(x));
    return r;
}
__device__ __forceinline__ void mma8(float* c, const uint32_t* a, const uint32_t* b) {
    asm volatile(
        "mma.sync.aligned.m16n8k8.row.col.f32.tf32.tf32.f32 "
        "{%0,%1,%2,%3}, {%4,%5,%6,%7}, {%8,%9}, {%0,%1,%2,%3};\n"
        : "+f"(c[0]), "+f"(c[1]), "+f"(c[2]), "+f"(c[3])
        : "r"(a[0]), "r"(a[1]), "r"(a[2]), "r"(a[3]), "r"(b[0]), "r"(b[1]));
}
__device__ __forceinline__ uint32_t smaddr(const void* p) {
    return (uint32_t)__cvta_generic_to_shared(p);
}
__device__ __forceinline__ void cp16(uint32_t dst, const void* src) {
    asm volatile("cp.async.ca.shared.global [%0], [%1], 16;\n" :: "r"(dst), "l"(src));
}
__device__ __forceinline__ void cpcommit() {
    asm volatile("cp.async.commit_group;\n");
}
template<int N>
__device__ __forceinline__ void cpwait() {
    asm volatile("cp.async.wait_group %0;\n" :: "n"(N));
}

// ---------------------------------------------------------------------------
// Pre-round: out[i] = tf32_rna(in[i]), vectorized float4.
// ---------------------------------------------------------------------------
__global__ __launch_bounds__(256) void round_tf32_kernel(
    const float4* __restrict__ in, float4* __restrict__ out, int n4)
{
    int i = blockIdx.x * blockDim.x + threadIdx.x;
    if (i < n4) {
        float4 v = in[i];
        v.x = rnd_tf32(v.x); v.y = rnd_tf32(v.y);
        v.z = rnd_tf32(v.z); v.w = rnd_tf32(v.w);
        out[i] = v;
    }
}

// ---------------------------------------------------------------------------
// GEMM: Y = X @ W^T + bias. Block tile 128x128, BK=32, double-buffered
// cp.async, 256 threads = 8 warps (4 M x 2 N), warp tile 32x64.
// Inputs pre-rounded to tf32 -> raw bits on the MMA path (no cvt in loop).
// split=1: write Y in [B,H,T,D], tf32-rounded; split=0: plain [M,E], fp32.
// smem: As[2][128][36] + Bs[2][128][36] = 73728 B (dynamic).
// ---------------------------------------------------------------------------
#define G_AS (128 * 36)
__global__ __launch_bounds__(256) void gemm_bias(
    const float* __restrict__ X, const float* __restrict__ W,
    const float* __restrict__ bias, float* __restrict__ Y, int split)
{
    extern __shared__ float sm[];
    float* As = sm;              // [2][128][36]
    float* Bs = sm + 2 * G_AS;   // [2][128][36]

    const int tid  = threadIdx.x;
    const int warp = tid >> 5, lane = tid & 31;
    const int wm   = warp >> 1, wn = warp & 1;
    const int g    = lane >> 2, t = lane & 3;
    const int m0   = blockIdx.x * 128;
    const int n0   = blockIdx.y * 128;

    auto issue = [&](int k0, int buf) {
        const float* Ag = X + (size_t)m0 * E_DIM + k0;
        const float* Bg = W + (size_t)n0 * E_DIM + k0;
        float* dA = As + buf * G_AS;
        float* dB = Bs + buf * G_AS;
#pragma unroll
        for (int i = 0; i < 4; i++) {
            int idx = tid + i * 256;          // 0..1023
            int r = idx >> 3, c4 = idx & 7;
            cp16(smaddr(dA + r * 36 + c4 * 4), Ag + (size_t)r * E_DIM + c4 * 4);
        }
#pragma unroll
        for (int i = 0; i < 4; i++) {
            int idx = tid + i * 256;
            int r = idx >> 3, c4 = idx & 7;
            cp16(smaddr(dB + r * 36 + c4 * 4), Bg + (size_t)r * E_DIM + c4 * 4);
        }
        cpcommit();
    };

    float acc[2][8][4];
#pragma unroll
    for (int i = 0; i < 2; i++)
#pragma unroll
        for (int j = 0; j < 8; j++)
#pragma unroll
            for (int r = 0; r < 4; r++) acc[i][j][r] = 0.f;

    issue(0, 0);

    for (int ks = 0; ks < 32; ks++) {
        if (ks + 1 < 32) { issue((ks + 1) * 32, (ks + 1) & 1); cpwait<1>(); }
        else             { cpwait<0>(); }
        __syncthreads();

        const float* A  = As + (ks & 1) * G_AS;
        const float* Bt = Bs + (ks & 1) * G_AS;

#pragma unroll
        for (int kk = 0; kk < 32; kk += 8) {
            uint32_t a[2][4];
#pragma unroll
            for (int mt = 0; mt < 2; mt++) {
                int row = wm * 32 + mt * 16;
                a[mt][0] = ftu(A[(row + g)     * 36 + kk + t]);
                a[mt][1] = ftu(A[(row + 8 + g) * 36 + kk + t]);
                a[mt][2] = ftu(A[(row + g)     * 36 + kk + t + 4]);
                a[mt][3] = ftu(A[(row + 8 + g) * 36 + kk + t + 4]);
            }
#pragma unroll
            for (int nt = 0; nt < 8; nt++) {
                int col = wn * 64 + nt * 8 + g;
                uint32_t b[2];
                b[0] = ftu(Bt[col * 36 + kk + t]);
                b[1] = ftu(Bt[col * 36 + kk + t + 4]);
                mma8(acc[0][nt], a[0], b);
                mma8(acc[1][nt], a[1], b);
            }
        }
        __syncthreads();
    }

    // Epilogue: bias + writeout (split outputs rounded for downstream MMAs)
#pragma unroll
    for (int mt = 0; mt < 2; mt++) {
#pragma unroll
        for (int nt = 0; nt < 8; nt++) {
            int mrow = m0 + wm * 32 + mt * 16 + g;
            int ncol = n0 + wn * 64 + nt * 8 + 2 * t;
            float b0 = bias[ncol], b1 = bias[ncol + 1];
            float v00 = acc[mt][nt][0] + b0, v01 = acc[mt][nt][1] + b1;
            float v10 = acc[mt][nt][2] + b0, v11 = acc[mt][nt][3] + b1;
            if (!split) {
                float* p0 = Y + (size_t)mrow * E_DIM + ncol;
                float* p1 = Y + (size_t)(mrow + 8) * E_DIM + ncol;
                p0[0] = v00; p0[1] = v01;
                p1[0] = v10; p1[1] = v11;
            } else {
                int h = ncol >> 6, d = ncol & 63;
                int bb = mrow >> 11, tt = mrow & 2047;
                size_t o0 = ((size_t)(bb * NH + h) * T_SEQ + tt) * HD + d;
                size_t o1 = o0 + 8 * HD;
                Y[o0] = rnd_tf32(v00); Y[o0 + 1] = rnd_tf32(v01);
                Y[o1] = rnd_tf32(v10); Y[o1 + 1] = rnd_tf32(v11);
            }
        }
    }
}

// ---------------------------------------------------------------------------
// Flash attention: grid (T/128, B*H), 256 threads (8 warps).
// Each warp owns 16 query rows; block = 128 queries x all 2048 keys.
// K/V streamed in 32-key tiles, double-buffered via cp.async.
// Q fragments cached in registers; sQ region reused as per-warp P scratch.
// Inputs pre-rounded tf32; P rounded once at the smem store.
// smem: sQ[128][68] + sK[2][32][68] + sV[2][32][72] = 70656 B (dynamic).
// ---------------------------------------------------------------------------
#define A_SQ  (128 * 68)
#define A_SKB (32 * 68)
#define A_SVB (32 * 72)
__global__ __launch_bounds__(256) void attn_kernel(
    const float* __restrict__ Q, const float* __restrict__ K,
    const float* __restrict__ V, float* __restrict__ O)
{
    extern __shared__ float sm[];
    float* sQ = sm;                     // [128][68]; reused as P scratch
    float* sK = sm + A_SQ;              // [2][32][68]
    float* sV = sK + 2 * A_SKB;         // [2][32][72]

    const int tid  = threadIdx.x;
    const int warp = tid >> 5, lane = tid & 31;
    const int g    = lane >> 2, t = lane & 3;
    const int q0   = blockIdx.x * 128;
    const int bh   = blockIdx.y;

    const float* Qb = Q + ((size_t)bh * T_SEQ + q0) * HD;
    const float* Kb = K + (size_t)bh * T_SEQ * HD;
    const float* Vb = V + (size_t)bh * T_SEQ * HD;

    auto issueKV = [&](int j, int buf) {
        const float* Kg = Kb + (size_t)j * 32 * HD;
        const float* Vg = Vb + (size_t)j * 32 * HD;
        float* dK = sK + buf * A_SKB;
        float* dV = sV + buf * A_SVB;
#pragma unroll
        for (int i = 0; i < 2; i++) {
            int idx = tid + i * 256;          // 0..511
            int r = idx >> 4, c4 = idx & 15;
            cp16(smaddr(dK + r * 68 + c4 * 4), Kg + r * HD + c4 * 4);
            cp16(smaddr(dV + r * 72 + c4 * 4), Vg + r * HD + c4 * 4);
        }
        cpcommit();
    };

    // Stage Q (group 0), then KV tile 0 (group 1)
#pragma unroll
    for (int i = 0; i < 8; i++) {
        int idx = tid + i * 256;              // 0..2047
        int r = idx >> 4, c4 = idx & 15;
        cp16(smaddr(sQ + r * 68 + c4 * 4), Qb + r * HD + c4 * 4);
    }
    cpcommit();
    issueKV(0, 0);
    cpwait<1>();          // Q complete
    __syncthreads();

    // Cache Q A-frags in registers (8 k-steps x 4 regs); sQ free afterwards.
    uint32_t qa[8][4];
    {
        int row = warp * 16;
#pragma unroll
        for (int kd = 0; kd < 8; kd++) {
            qa[kd][0] = ftu(sQ[(row + g)     * 68 + kd * 8 + t]);
            qa[kd][1] = ftu(sQ[(row + 8 + g) * 68 + kd * 8 + t]);
            qa[kd][2] = ftu(sQ[(row + g)     * 68 + kd * 8 + t + 4]);
            qa[kd][3] = ftu(sQ[(row + 8 + g) * 68 + kd * 8 + t + 4]);
        }
    }
    // Per-warp P scratch carved out of the (now dead) sQ region.
    float* sP = sQ + warp * (16 * 36);   // [16][36], 8 warps -> 4608 floats

    float m0v = -1e30f, m1v = -1e30f;
    float l0 = 0.f, l1 = 0.f;
    float o[8][4];
#pragma unroll
    for (int df = 0; df < 8; df++)
#pragma unroll
        for (int r = 0; r < 4; r++) o[df][r] = 0.f;

    const float SC = 0.125f * 1.44269504088896f;   // 1/sqrt(64) * log2(e)

    for (int j = 0; j < T_SEQ / 32; j++) {
        if (j + 1 < T_SEQ / 32) { issueKV(j + 1, (j + 1) & 1); cpwait<1>(); }
        else                    { cpwait<0>(); }
        __syncthreads();   // also orders first P-store after all qa loads (j=0)

        const float* Kt = sK + (j & 1) * A_SKB;
        const float* Vt = sV + (j & 1) * A_SVB;

        // ---- S = Q K^T : 16 q-rows x 32 keys, k-dim 64 ----
        float s[4][4];
#pragma unroll
        for (int nt = 0; nt < 4; nt++)
#pragma unroll
            for (int r = 0; r < 4; r++) s[nt][r] = 0.f;

#pragma unroll
        for (int kd = 0; kd < 8; kd++) {
#pragma unroll
            for (int nt = 0; nt < 4; nt++) {
                uint32_t b[2];
                b[0] = ftu(Kt[(nt * 8 + g) * 68 + kd * 8 + t]);
                b[1] = ftu(Kt[(nt * 8 + g) * 68 + kd * 8 + t + 4]);
                mma8(s[nt], qa[kd], b);
            }
        }

        // ---- online softmax (base-2) ----
        float mx0 = -1e30f, mx1 = -1e30f;
#pragma unroll
        for (int nt = 0; nt < 4; nt++) {
            s[nt][0] *= SC; s[nt][1] *= SC;
            s[nt][2] *= SC; s[nt][3] *= SC;
            mx0 = fmaxf(mx0, fmaxf(s[nt][0], s[nt][1]));
            mx1 = fmaxf(mx1, fmaxf(s[nt][2], s[nt][3]));
        }
        mx0 = fmaxf(mx0, __shfl_xor_sync(0xffffffffu, mx0, 1));
        mx0 = fmaxf(mx0, __shfl_xor_sync(0xffffffffu, mx0, 2));
        mx1 = fmaxf(mx1, __shfl_xor_sync(0xffffffffu, mx1, 1));
        mx1 = fmaxf(mx1, __shfl_xor_sync(0xffffffffu, mx1, 2));

        float mn0 = fmaxf(m0v, mx0), mn1 = fmaxf(m1v, mx1);
        float al0 = ex2(m0v - mn0),  al1 = ex2(m1v - mn1);

        float rs0 = 0.f, rs1 = 0.f;
#pragma unroll
        for (int nt = 0; nt < 4; nt++) {
            s[nt][0] = ex2(s[nt][0] - mn0);
            s[nt][1] = ex2(s[nt][1] - mn0);
            s[nt][2] = ex2(s[nt][2] - mn1);
            s[nt][3] = ex2(s[nt][3] - mn1);
            rs0 += s[nt][0] + s[nt][1];
            rs1 += s[nt][2] + s[nt][3];
        }
        rs0 += __shfl_xor_sync(0xffffffffu, rs0, 1);
        rs0 += __shfl_xor_sync(0xffffffffu, rs0, 2);
        rs1 += __shfl_xor_sync(0xffffffffu, rs1, 1);
        rs1 += __shfl_xor_sync(0xffffffffu, rs1, 2);

        l0 = l0 * al0 + rs0;  l1 = l1 * al1 + rs1;
        m0v = mn0;            m1v = mn1;

#pragma unroll
        for (int df = 0; df < 8; df++) {
            o[df][0] *= al0; o[df][1] *= al0;
            o[df][2] *= al1; o[df][3] *= al1;
        }

        // ---- P round-trip through per-warp smem (C-frag -> A-frag),
        //      RNA-rounded once here so the MMA feed below is exact tf32 ----
#pragma unroll
        for (int nt = 0; nt < 4; nt++) {
            sP[g       * 36 + nt * 8 + 2 * t]     = rnd_tf32(s[nt][0]);
            sP[g       * 36 + nt * 8 + 2 * t + 1] = rnd_tf32(s[nt][1]);
            sP[(g + 8) * 36 + nt * 8 + 2 * t]     = rnd_tf32(s[nt][2]);
            sP[(g + 8) * 36 + nt * 8 + 2 * t + 1] = rnd_tf32(s[nt][3]);
        }
        __syncwarp();

        // ---- O += P @ V : 16 x 64, k-dim 32 keys ----
#pragma unroll
        for (int kk = 0; kk < 4; kk++) {
            uint32_t pa[4];
            pa[0] = ftu(sP[g       * 36 + kk * 8 + t]);
            pa[1] = ftu(sP[(g + 8) * 36 + kk * 8 + t]);
            pa[2] = ftu(sP[g       * 36 + kk * 8 + t + 4]);
            pa[3] = ftu(sP[(g + 8) * 36 + kk * 8 + t + 4]);
#pragma unroll
            for (int df = 0; df < 8; df++) {
                uint32_t b[2];
                b[0] = ftu(Vt[(kk * 8 + t)     * 72 + df * 8 + g]);
                b[1] = ftu(Vt[(kk * 8 + t + 4) * 72 + df * 8 + g]);
                mma8(o[df], pa, b);
            }
        }
        __syncthreads();   // all warps done with current K/V buffer
    }

    // ---- epilogue: normalize, round for the final GEMM, write [B,T,E] ----
    float inv0 = 1.f / l0, inv1 = 1.f / l1;
    int bb = bh >> 4, h = bh & 15;
    int r0 = q0 + warp * 16 + g;
#pragma unroll
    for (int df = 0; df < 8; df++) {
        int d = df * 8 + 2 * t;
        size_t base0 = ((size_t)bb * T_SEQ + r0) * E_DIM + h * HD + d;
        size_t base1 = base0 + (size_t)8 * E_DIM;
        O[base0]     = rnd_tf32(o[df][0] * inv0);
        O[base0 + 1] = rnd_tf32(o[df][1] * inv0);
        O[base1]     = rnd_tf32(o[df][2] * inv1);
        O[base1 + 1] = rnd_tf32(o[df][3] * inv1);
    }
}

// ---------------------------------------------------------------------------
// Launcher
// ---------------------------------------------------------------------------
#define GEMM_SMEM  (4 * G_AS * 4)                        // 73728 B
#define ATTN_SMEM  ((A_SQ + 2 * A_SKB + 2 * A_SVB) * 4)  // 70656 B

extern "C" void kernel_launch(void* const* d_in, const int* in_sizes, int n_in,
                              void* d_out, int out_size)
{
    const float* x  = (const float*)d_in[0];
    const float* Wq = (const float*)d_in[1];
    const float* bq = (const float*)d_in[2];
    const float* Wk = (const float*)d_in[3];
    const float* bk = (const float*)d_in[4];
    const float* Wv = (const float*)d_in[5];
    const float* bv = (const float*)d_in[6];
    const float* Wo = (const float*)d_in[7];
    const float* bo = (const float*)d_in[8];

    float *q, *k, *v, *ctx, *xr, *wq, *wk, *wv, *wo;
    cudaGetSymbolAddress((void**)&q,   g_q);
    cudaGetSymbolAddress((void**)&k,   g_k);
    cudaGetSymbolAddress((void**)&v,   g_v);
    cudaGetSymbolAddress((void**)&ctx, g_ctx);
    cudaGetSymbolAddress((void**)&xr,  g_x);
    cudaGetSymbolAddress((void**)&wq,  g_wq);
    cudaGetSymbolAddress((void**)&wk,  g_wk);
    cudaGetSymbolAddress((void**)&wv,  g_wv);
    cudaGetSymbolAddress((void**)&wo,  g_wo);

    cudaFuncSetAttribute(gemm_bias, cudaFuncAttributeMaxDynamicSharedMemorySize, GEMM_SMEM);
    cudaFuncSetAttribute(attn_kernel, cudaFuncAttributeMaxDynamicSharedMemorySize, ATTN_SMEM);

    // Pre-round x and weights to tf32 (RNA) so the GEMM MMA path is exact.
    const int NX4 = (M_TOT * E_DIM) / 4;    // 2,097,152
    const int NW4 = (E_DIM * E_DIM) / 4;    // 262,144
    round_tf32_kernel<<<NX4 / 256, 256>>>((const float4*)x,  (float4*)xr, NX4);
    round_tf32_kernel<<<NW4 / 256, 256>>>((const float4*)Wq, (float4*)wq, NW4);
    round_tf32_kernel<<<NW4 / 256, 256>>>((const float4*)Wk, (float4*)wk, NW4);
    round_tf32_kernel<<<NW4 / 256, 256>>>((const float4*)Wv, (float4*)wv, NW4);
    round_tf32_kernel<<<NW4 / 256, 256>>>((const float4*)Wo, (float4*)wo, NW4);

    dim3 ggrid(M_TOT / 128, E_DIM / 128);   // (64, 8)

    gemm_bias<<<ggrid, 256, GEMM_SMEM>>>(xr, wq, bq, q, 1);
    gemm_bias<<<ggrid, 256, GEMM_SMEM>>>(xr, wk, bk, k, 1);
    gemm_bias<<<ggrid, 256, GEMM_SMEM>>>(xr, wv, bv, v, 1);

    attn_kernel<<<dim3(T_SEQ / 128, B_SZ * NH), 256, ATTN_SMEM>>>(q, k, v, ctx);

    gemm_bias<<<ggrid, 256, GEMM_SMEM>>>(ctx, wo, bo, (float*)d_out, 0);
}

// round 13
// speedup vs baseline: 1.5967x; 1.4362x over previous
#include <cuda_runtime.h>
#include <cstdint>

// Problem constants (fixed-shape problem)
#define B_SZ   4
#define T_SEQ  2048
#define E_DIM  1024
#define NH     16
#define HD     64
#define M_TOT  (B_SZ * T_SEQ)   // 8192

// ---------------------------------------------------------------------------
// Scratch (allocation-free rule: __device__ globals)
// ---------------------------------------------------------------------------
__device__ float g_q[(size_t)M_TOT * E_DIM];    // [B,H,T,D] (tf32-rounded)
__device__ float g_k[(size_t)M_TOT * E_DIM];    // [B,H,T,D] (tf32-rounded)
__device__ float g_v[(size_t)M_TOT * E_DIM];    // [B,H,T,D] (tf32-rounded)
__device__ float g_ctx[(size_t)M_TOT * E_DIM];  // [B,T,E]   (tf32-rounded)
__device__ float g_x [(size_t)M_TOT * E_DIM];   // tf32-rounded copy of x
__device__ float g_wq[(size_t)E_DIM * E_DIM];   // tf32-rounded weights
__device__ float g_wk[(size_t)E_DIM * E_DIM];
__device__ float g_wv[(size_t)E_DIM * E_DIM];
__device__ float g_wo[(size_t)E_DIM * E_DIM];

// ---------------------------------------------------------------------------
// helpers
// ---------------------------------------------------------------------------
// All MMA operands are RNA-rounded to tf32 BEFORE they reach smem, so the
// inner loops feed raw fp32 bit patterns (hardware truncation is then exact).
__device__ __forceinline__ uint32_t ftu(float x) { return __float_as_uint(x); }

__device__ __forceinline__ float rnd_tf32(float x) {
    uint32_t r;
    asm("cvt.rna.tf32.f32 %0, %1;" : "=r"(r) : "f"(x));
    return __uint_as_float(r);
}
__device__ __forceinline__ float ex2(float x) {
    float r;
    asm("ex2.approx.f32 %0, %1;" : "=f"(r) : "f"(x));
    return r;
}
__device__ __forceinline__ void mma8(float* c, const uint32_t* a, const uint32_t* b) {
    asm volatile(
        "mma.sync.aligned.m16n8k8.row.col.f32.tf32.tf32.f32 "
        "{%0,%1,%2,%3}, {%4,%5,%6,%7}, {%8,%9}, {%0,%1,%2,%3};\n"
        : "+f"(c[0]), "+f"(c[1]), "+f"(c[2]), "+f"(c[3])
        : "r"(a[0]), "r"(a[1]), "r"(a[2]), "r"(a[3]), "r"(b[0]), "r"(b[1]));
}
__device__ __forceinline__ uint32_t smaddr(const void* p) {
    return (uint32_t)__cvta_generic_to_shared(p);
}
__device__ __forceinline__ void cp16(uint32_t dst, const void* src) {
    asm volatile("cp.async.ca.shared.global [%0], [%1], 16;\n" :: "r"(dst), "l"(src));
}
__device__ __forceinline__ void cpcommit() {
    asm volatile("cp.async.commit_group;\n");
}
template<int N>
__device__ __forceinline__ void cpwait() {
    asm volatile("cp.async.wait_group %0;\n" :: "n"(N));
}

// ---------------------------------------------------------------------------
// Pre-round: out[i] = tf32_rna(in[i]), vectorized float4.
// ---------------------------------------------------------------------------
__global__ __launch_bounds__(256) void round_tf32_kernel(
    const float4* __restrict__ in, float4* __restrict__ out, int n4)
{
    int i = blockIdx.x * blockDim.x + threadIdx.x;
    if (i < n4) {
        float4 v = in[i];
        v.x = rnd_tf32(v.x); v.y = rnd_tf32(v.y);
        v.z = rnd_tf32(v.z); v.w = rnd_tf32(v.w);
        out[i] = v;
    }
}

// ---------------------------------------------------------------------------
// GEMM: Y = X @ W^T + bias.  R3-proven 128x64 block tile, BK=32, now with
// cp.async double-buffering (inputs pre-rounded tf32 -> raw byte copies).
// 256 threads = 8 warps (4 M x 2 N), warp tile 32x32.
// split=1: write Y in [B,H,T,D], tf32-rounded; split=0: plain [M,E], fp32.
// smem: As[2][128][36] + Bs[2][64][36] floats = 55296 B (dynamic).
// ---------------------------------------------------------------------------
#define G_A1 (128 * 36)
#define G_B1 (64 * 36)
__global__ __launch_bounds__(256) void gemm_bias(
    const float* __restrict__ X, const float* __restrict__ W,
    const float* __restrict__ bias, float* __restrict__ Y, int split)
{
    extern __shared__ float sm[];
    float* As = sm;              // [2][128][36]
    float* Bs = sm + 2 * G_A1;   // [2][64][36]

    const int tid  = threadIdx.x;
    const int warp = tid >> 5, lane = tid & 31;
    const int wm   = warp >> 1, wn = warp & 1;
    const int g    = lane >> 2, t = lane & 3;
    const int m0   = blockIdx.x * 128;
    const int n0   = blockIdx.y * 64;

    auto issue = [&](int k0, int buf) {
        const float* Ag = X + (size_t)m0 * E_DIM + k0;
        const float* Bg = W + (size_t)n0 * E_DIM + k0;
        float* dA = As + buf * G_A1;
        float* dB = Bs + buf * G_B1;
#pragma unroll
        for (int i = 0; i < 4; i++) {
            int idx = tid + i * 256;          // 0..1023  (128 rows x 8 float4)
            int r = idx >> 3, c4 = idx & 7;
            cp16(smaddr(dA + r * 36 + c4 * 4), Ag + (size_t)r * E_DIM + c4 * 4);
        }
#pragma unroll
        for (int i = 0; i < 2; i++) {
            int idx = tid + i * 256;          // 0..511   (64 rows x 8 float4)
            int r = idx >> 3, c4 = idx & 7;
            cp16(smaddr(dB + r * 36 + c4 * 4), Bg + (size_t)r * E_DIM + c4 * 4);
        }
        cpcommit();
    };

    float acc[2][4][4];
#pragma unroll
    for (int i = 0; i < 2; i++)
#pragma unroll
        for (int j = 0; j < 4; j++)
#pragma unroll
            for (int r = 0; r < 4; r++) acc[i][j][r] = 0.f;

    issue(0, 0);

    for (int ks = 0; ks < 32; ks++) {
        if (ks + 1 < 32) { issue((ks + 1) * 32, (ks + 1) & 1); cpwait<1>(); }
        else             { cpwait<0>(); }
        __syncthreads();

        const float* A  = As + (ks & 1) * G_A1;
        const float* Bt = Bs + (ks & 1) * G_B1;

#pragma unroll
        for (int kk = 0; kk < 32; kk += 8) {
            uint32_t a[2][4], b[4][2];
#pragma unroll
            for (int mt = 0; mt < 2; mt++) {
                int row = wm * 32 + mt * 16;
                a[mt][0] = ftu(A[(row + g)     * 36 + kk + t]);
                a[mt][1] = ftu(A[(row + 8 + g) * 36 + kk + t]);
                a[mt][2] = ftu(A[(row + g)     * 36 + kk + t + 4]);
                a[mt][3] = ftu(A[(row + 8 + g) * 36 + kk + t + 4]);
            }
#pragma unroll
            for (int nt = 0; nt < 4; nt++) {
                int col = wn * 32 + nt * 8 + g;
                b[nt][0] = ftu(Bt[col * 36 + kk + t]);
                b[nt][1] = ftu(Bt[col * 36 + kk + t + 4]);
            }
#pragma unroll
            for (int mt = 0; mt < 2; mt++)
#pragma unroll
                for (int nt = 0; nt < 4; nt++)
                    mma8(acc[mt][nt], a[mt], b[nt]);
        }
        __syncthreads();
    }

    // Epilogue: bias + writeout (split outputs rounded for downstream MMAs)
#pragma unroll
    for (int mt = 0; mt < 2; mt++) {
#pragma unroll
        for (int nt = 0; nt < 4; nt++) {
            int mrow = m0 + wm * 32 + mt * 16 + g;
            int ncol = n0 + wn * 32 + nt * 8 + 2 * t;
            float b0 = bias[ncol], b1 = bias[ncol + 1];
            float v00 = acc[mt][nt][0] + b0, v01 = acc[mt][nt][1] + b1;
            float v10 = acc[mt][nt][2] + b0, v11 = acc[mt][nt][3] + b1;
            if (!split) {
                float* p0 = Y + (size_t)mrow * E_DIM + ncol;
                float* p1 = Y + (size_t)(mrow + 8) * E_DIM + ncol;
                p0[0] = v00; p0[1] = v01;
                p1[0] = v10; p1[1] = v11;
            } else {
                int h = ncol >> 6, d = ncol & 63;
                int bb = mrow >> 11, tt = mrow & 2047;
                size_t o0 = ((size_t)(bb * NH + h) * T_SEQ + tt) * HD + d;
                size_t o1 = o0 + 8 * HD;
                Y[o0] = rnd_tf32(v00); Y[o0 + 1] = rnd_tf32(v01);
                Y[o1] = rnd_tf32(v10); Y[o1 + 1] = rnd_tf32(v11);
            }
        }
    }
}

// ---------------------------------------------------------------------------
// Flash attention: grid (T/64, B*H) = (32, 64), 128 threads (4 warps) —
// the R3-measured structure. Each warp owns 16 query rows; block = 64
// queries x all 2048 keys. K/V streamed in 32-key tiles, double-buffered
// via cp.async (inputs pre-rounded tf32, raw byte copies, zero staging cvt).
// Q fragments cached in registers; sQ region reused as per-warp P scratch.
// smem: sQ[64][68] + sK[2][32][68] + sV[2][32][72] = 53248 B (dynamic).
// ---------------------------------------------------------------------------
#define A_SQ  (64 * 68)
#define A_SKB (32 * 68)
#define A_SVB (32 * 72)
__global__ __launch_bounds__(128) void attn_kernel(
    const float* __restrict__ Q, const float* __restrict__ K,
    const float* __restrict__ V, float* __restrict__ O)
{
    extern __shared__ float sm[];
    float* sQ = sm;                     // [64][68]; reused as P scratch
    float* sK = sm + A_SQ;              // [2][32][68]
    float* sV = sK + 2 * A_SKB;         // [2][32][72]

    const int tid  = threadIdx.x;
    const int warp = tid >> 5, lane = tid & 31;
    const int g    = lane >> 2, t = lane & 3;
    const int q0   = blockIdx.x * 64;
    const int bh   = blockIdx.y;

    const float* Qb = Q + ((size_t)bh * T_SEQ + q0) * HD;
    const float* Kb = K + (size_t)bh * T_SEQ * HD;
    const float* Vb = V + (size_t)bh * T_SEQ * HD;

    auto issueKV = [&](int j, int buf) {
        const float* Kg = Kb + (size_t)j * 32 * HD;
        const float* Vg = Vb + (size_t)j * 32 * HD;
        float* dK = sK + buf * A_SKB;
        float* dV = sV + buf * A_SVB;
#pragma unroll
        for (int i = 0; i < 4; i++) {
            int idx = tid + i * 128;          // 0..511  (32 rows x 16 float4)
            int r = idx >> 4, c4 = idx & 15;
            cp16(smaddr(dK + r * 68 + c4 * 4), Kg + r * HD + c4 * 4);
            cp16(smaddr(dV + r * 72 + c4 * 4), Vg + r * HD + c4 * 4);
        }
        cpcommit();
    };

    // Stage Q (group 0), then KV tile 0 (group 1)
#pragma unroll
    for (int i = 0; i < 8; i++) {
        int idx = tid + i * 128;              // 0..1023 (64 rows x 16 float4)
        int r = idx >> 4, c4 = idx & 15;
        cp16(smaddr(sQ + r * 68 + c4 * 4), Qb + r * HD + c4 * 4);
    }
    cpcommit();
    issueKV(0, 0);
    cpwait<1>();          // Q complete
    __syncthreads();

    // Cache Q A-frags in registers (8 k-steps x 4 regs); sQ free afterwards.
    uint32_t qa[8][4];
    {
        int row = warp * 16;
#pragma unroll
        for (int kd = 0; kd < 8; kd++) {
            qa[kd][0] = ftu(sQ[(row + g)     * 68 + kd * 8 + t]);
            qa[kd][1] = ftu(sQ[(row + 8 + g) * 68 + kd * 8 + t]);
            qa[kd][2] = ftu(sQ[(row + g)     * 68 + kd * 8 + t + 4]);
            qa[kd][3] = ftu(sQ[(row + 8 + g) * 68 + kd * 8 + t + 4]);
        }
    }
    // Per-warp P scratch carved out of the (now dead) sQ region.
    float* sP = sQ + warp * (16 * 36);   // [16][36], 4 warps -> 2304 floats

    float m0v = -1e30f, m1v = -1e30f;
    float l0 = 0.f, l1 = 0.f;
    float o[8][4];
#pragma unroll
    for (int df = 0; df < 8; df++)
#pragma unroll
        for (int r = 0; r < 4; r++) o[df][r] = 0.f;

    const float SC = 0.125f * 1.44269504088896f;   // 1/sqrt(64) * log2(e)

    for (int j = 0; j < T_SEQ / 32; j++) {
        if (j + 1 < T_SEQ / 32) { issueKV(j + 1, (j + 1) & 1); cpwait<1>(); }
        else                    { cpwait<0>(); }
        __syncthreads();   // also orders first P-store after all qa loads (j=0)

        const float* Kt = sK + (j & 1) * A_SKB;
        const float* Vt = sV + (j & 1) * A_SVB;

        // ---- S = Q K^T : 16 q-rows x 32 keys, k-dim 64 ----
        float s[4][4];
#pragma unroll
        for (int nt = 0; nt < 4; nt++)
#pragma unroll
            for (int r = 0; r < 4; r++) s[nt][r] = 0.f;

#pragma unroll
        for (int kd = 0; kd < 8; kd++) {
#pragma unroll
            for (int nt = 0; nt < 4; nt++) {
                uint32_t b[2];
                b[0] = ftu(Kt[(nt * 8 + g) * 68 + kd * 8 + t]);
                b[1] = ftu(Kt[(nt * 8 + g) * 68 + kd * 8 + t + 4]);
                mma8(s[nt], qa[kd], b);
            }
        }

        // ---- online softmax (base-2) ----
        float mx0 = -1e30f, mx1 = -1e30f;
#pragma unroll
        for (int nt = 0; nt < 4; nt++) {
            s[nt][0] *= SC; s[nt][1] *= SC;
            s[nt][2] *= SC; s[nt][3] *= SC;
            mx0 = fmaxf(mx0, fmaxf(s[nt][0], s[nt][1]));
            mx1 = fmaxf(mx1, fmaxf(s[nt][2], s[nt][3]));
        }
        mx0 = fmaxf(mx0, __shfl_xor_sync(0xffffffffu, mx0, 1));
        mx0 = fmaxf(mx0, __shfl_xor_sync(0xffffffffu, mx0, 2));
        mx1 = fmaxf(mx1, __shfl_xor_sync(0xffffffffu, mx1, 1));
        mx1 = fmaxf(mx1, __shfl_xor_sync(0xffffffffu, mx1, 2));

        float mn0 = fmaxf(m0v, mx0), mn1 = fmaxf(m1v, mx1);
        float al0 = ex2(m0v - mn0),  al1 = ex2(m1v - mn1);

        float rs0 = 0.f, rs1 = 0.f;
#pragma unroll
        for (int nt = 0; nt < 4; nt++) {
            s[nt][0] = ex2(s[nt][0] - mn0);
            s[nt][1] = ex2(s[nt][1] - mn0);
            s[nt][2] = ex2(s[nt][2] - mn1);
            s[nt][3] = ex2(s[nt][3] - mn1);
            rs0 += s[nt][0] + s[nt][1];
            rs1 += s[nt][2] + s[nt][3];
        }
        rs0 += __shfl_xor_sync(0xffffffffu, rs0, 1);
        rs0 += __shfl_xor_sync(0xffffffffu, rs0, 2);
        rs1 += __shfl_xor_sync(0xffffffffu, rs1, 1);
        rs1 += __shfl_xor_sync(0xffffffffu, rs1, 2);

        l0 = l0 * al0 + rs0;  l1 = l1 * al1 + rs1;
        m0v = mn0;            m1v = mn1;

#pragma unroll
        for (int df = 0; df < 8; df++) {
            o[df][0] *= al0; o[df][1] *= al0;
            o[df][2] *= al1; o[df][3] *= al1;
        }

        // ---- P round-trip through per-warp smem (C-frag -> A-frag),
        //      RNA-rounded once here so the MMA feed below is exact tf32 ----
#pragma unroll
        for (int nt = 0; nt < 4; nt++) {
            sP[g       * 36 + nt * 8 + 2 * t]     = rnd_tf32(s[nt][0]);
            sP[g       * 36 + nt * 8 + 2 * t + 1] = rnd_tf32(s[nt][1]);
            sP[(g + 8) * 36 + nt * 8 + 2 * t]     = rnd_tf32(s[nt][2]);
            sP[(g + 8) * 36 + nt * 8 + 2 * t + 1] = rnd_tf32(s[nt][3]);
        }
        __syncwarp();

        // ---- O += P @ V : 16 x 64, k-dim 32 keys ----
#pragma unroll
        for (int kk = 0; kk < 4; kk++) {
            uint32_t pa[4];
            pa[0] = ftu(sP[g       * 36 + kk * 8 + t]);
            pa[1] = ftu(sP[(g + 8) * 36 + kk * 8 + t]);
            pa[2] = ftu(sP[g       * 36 + kk * 8 + t + 4]);
            pa[3] = ftu(sP[(g + 8) * 36 + kk * 8 + t + 4]);
#pragma unroll
            for (int df = 0; df < 8; df++) {
                uint32_t b[2];
                b[0] = ftu(Vt[(kk * 8 + t)     * 72 + df * 8 + g]);
                b[1] = ftu(Vt[(kk * 8 + t + 4) * 72 + df * 8 + g]);
                mma8(o[df], pa, b);
            }
        }
        __syncthreads();   // all warps done with current K/V buffer
    }

    // ---- epilogue: normalize, round for the final GEMM, write [B,T,E] ----
    float inv0 = 1.f / l0, inv1 = 1.f / l1;
    int bb = bh >> 4, h = bh & 15;
    int r0 = q0 + warp * 16 + g;
#pragma unroll
    for (int df = 0; df < 8; df++) {
        int d = df * 8 + 2 * t;
        size_t base0 = ((size_t)bb * T_SEQ + r0) * E_DIM + h * HD + d;
        size_t base1 = base0 + (size_t)8 * E_DIM;
        O[base0]     = rnd_tf32(o[df][0] * inv0);
        O[base0 + 1] = rnd_tf32(o[df][1] * inv0);
        O[base1]     = rnd_tf32(o[df][2] * inv1);
        O[base1 + 1] = rnd_tf32(o[df][3] * inv1);
    }
}

// ---------------------------------------------------------------------------
// Launcher
// ---------------------------------------------------------------------------
#define GEMM_SMEM  ((2 * G_A1 + 2 * G_B1) * 4)           // 55296 B
#define ATTN_SMEM  ((A_SQ + 2 * A_SKB + 2 * A_SVB) * 4)  // 53248 B

extern "C" void kernel_launch(void* const* d_in, const int* in_sizes, int n_in,
                              void* d_out, int out_size)
{
    const float* x  = (const float*)d_in[0];
    const float* Wq = (const float*)d_in[1];
    const float* bq = (const float*)d_in[2];
    const float* Wk = (const float*)d_in[3];
    const float* bk = (const float*)d_in[4];
    const float* Wv = (const float*)d_in[5];
    const float* bv = (const float*)d_in[6];
    const float* Wo = (const float*)d_in[7];
    const float* bo = (const float*)d_in[8];

    float *q, *k, *v, *ctx, *xr, *wq, *wk, *wv, *wo;
    cudaGetSymbolAddress((void**)&q,   g_q);
    cudaGetSymbolAddress((void**)&k,   g_k);
    cudaGetSymbolAddress((void**)&v,   g_v);
    cudaGetSymbolAddress((void**)&ctx, g_ctx);
    cudaGetSymbolAddress((void**)&xr,  g_x);
    cudaGetSymbolAddress((void**)&wq,  g_wq);
    cudaGetSymbolAddress((void**)&wk,  g_wk);
    cudaGetSymbolAddress((void**)&wv,  g_wv);
    cudaGetSymbolAddress((void**)&wo,  g_wo);

    cudaFuncSetAttribute(gemm_bias, cudaFuncAttributeMaxDynamicSharedMemorySize, GEMM_SMEM);
    cudaFuncSetAttribute(attn_kernel, cudaFuncAttributeMaxDynamicSharedMemorySize, ATTN_SMEM);

    // Pre-round x and weights to tf32 (RNA) so all MMA feeds are exact.
    const int NX4 = (M_TOT * E_DIM) / 4;    // 2,097,152
    const int NW4 = (E_DIM * E_DIM) / 4;    // 262,144
    round_tf32_kernel<<<NX4 / 256, 256>>>((const float4*)x,  (float4*)xr, NX4);
    round_tf32_kernel<<<NW4 / 256, 256>>>((const float4*)Wq, (float4*)wq, NW4);
    round_tf32_kernel<<<NW4 / 256, 256>>>((const float4*)Wk, (float4*)wk, NW4);
    round_tf32_kernel<<<NW4 / 256, 256>>>((const float4*)Wv, (float4*)wv, NW4);
    round_tf32_kernel<<<NW4 / 256, 256>>>((const float4*)Wo, (float4*)wo, NW4);

    dim3 ggrid(M_TOT / 128, E_DIM / 64);    // (64, 16)

    gemm_bias<<<ggrid, 256, GEMM_SMEM>>>(xr, wq, bq, q, 1);
    gemm_bias<<<ggrid, 256, GEMM_SMEM>>>(xr, wk, bk, k, 1);
    gemm_bias<<<ggrid, 256, GEMM_SMEM>>>(xr, wv, bv, v, 1);

    attn_kernel<<<dim3(T_SEQ / 64, B_SZ * NH), 128, ATTN_SMEM>>>(q, k, v, ctx);

    gemm_bias<<<ggrid, 256, GEMM_SMEM>>>(ctx, wo, bo, (float*)d_out, 0);
}